// round 6
// baseline (speedup 1.0000x reference)
#include <cuda_runtime.h>
#include <math_constants.h>

// out = minmax_normalize( bicubic_up2x( LL[:, 0:8] ) )
// All other iqwt terms carry sum(gh)=sum(fl)=sum(fh)=0 (f32 residue < 3e-7);
// the surviving sg^2 scalar cancels in the min-max normalization.
//
// memset node zeroes/sets g_red sentinels (both 0xFFFFFFFF).
// Pass 1: pipelined upsample, min/max -> 2 atomics per block.
// Pass 2: pipelined recompute (input L2-resident), fused normalize, float4 stores.
// Each block: 4 tiles, cp.async double-buffered (load tile t+1 || compute tile t).

#define THREADS 256
#define NT      4                     // tiles per block
#define TILE_J  8                     // input rows per tile -> 16 output rows
#define IN_ROWS 12                    // 8 + 4 halo
#define SMEM_W  264                   // 4 pad | 256 | 4 pad  (16B-aligned windows)
#define N_IN    256
#define N_OUT   512
#define N_IMG   64
#define TILES_PER_IMG 32
#define GRID (N_IMG * TILES_PER_IMG / NT)   // 512

// bicubic a=-0.75, src = 0.5*i - 0.25
#define WE0 (-0.03515625f)
#define WE1 ( 0.26171875f)
#define WE2 ( 0.87890625f)
#define WE3 (-0.10546875f)
#define WO0 (-0.10546875f)
#define WO1 ( 0.87890625f)
#define WO2 ( 0.26171875f)
#define WO3 (-0.03515625f)

__device__ unsigned int g_red[2];   // [0]=min(enc(v)), [1]=min(enc(-v))

__device__ __forceinline__ unsigned int encf(float f) {
    unsigned int u = __float_as_uint(f);
    return (u & 0x80000000u) ? ~u : (u | 0x80000000u);
}
__device__ __forceinline__ float decf(unsigned int e) {
    unsigned int u = (e & 0x80000000u) ? (e ^ 0x80000000u) : ~e;
    return __uint_as_float(u);
}

__device__ __forceinline__ void cp16(void* dst, const void* src) {
    unsigned int d = (unsigned int)__cvta_generic_to_shared(dst);
    asm volatile("cp.async.cg.shared.global [%0], [%1], 16;" :: "r"(d), "l"(src));
}
__device__ __forceinline__ void cp4(void* dst, const void* src) {
    unsigned int d = (unsigned int)__cvta_generic_to_shared(dst);
    asm volatile("cp.async.ca.shared.global [%0], [%1], 4;" :: "r"(d), "l"(src));
}

__device__ __forceinline__ void issue_tile(float (*sb)[SMEM_W],
                                           const float* __restrict__ src,
                                           int jbase, int t) {
    // 768 16B copies: thread t does 3; input col 4qc -> smem col 4qc+4.
#pragma unroll
    for (int i = 0; i < 3; i++) {
        const int f  = t + i * THREADS;
        const int rr = f >> 6;
        const int qc = f & 63;
        const int gr = min(max(jbase - 2 + rr, 0), N_IN - 1);
        cp16(&sb[rr][4 * qc + 4], src + gr * N_IN + 4 * qc);
    }
    // Replicate halo: smem cols 2,3 = input col 0; cols 260,261 = input col 255.
    if (t < 24) {
        const int rr   = t % IN_ROWS;
        const int side = t / IN_ROWS;
        const int gr = min(max(jbase - 2 + rr, 0), N_IN - 1);
        if (side == 0) {
            const float* p = src + gr * N_IN;
            cp4(&sb[rr][2], p); cp4(&sb[rr][3], p);
        } else {
            const float* p = src + gr * N_IN + (N_IN - 1);
            cp4(&sb[rr][260], p); cp4(&sb[rr][261], p);
        }
    }
}

template <bool WRITE>
__global__ __launch_bounds__(THREADS)
void qwt_up_kernel(const float* __restrict__ LL, float* __restrict__ out) {
    __shared__ __align__(16) float s[2][IN_ROWS][SMEM_W];

    const int t     = threadIdx.x;
    const int tile0 = blockIdx.x * NT;       // 4 tiles, all within one image
    const int img   = tile0 >> 5;            // 0..63
    const int b     = img >> 3;
    const int ch    = img & 7;               // lglg = LL channels 0..7
    const float* __restrict__ src = LL + (size_t)(b * 32 + ch) * (N_IN * N_IN);

    const int q = t & 63;                    // output cols 8q..8q+7
    const int g = t >> 6;                    // block-local out rows 4g..4g+3

    float scale = 1.0f, bias = 0.0f;
    if (WRITE) {
        const float mn =  decf(g_red[0]);
        const float mx = -decf(g_red[1]);
        scale = 1.0f / (mx - mn);
        bias  = -mn * scale;
    }

    float lmin =  CUDART_INF_F;
    float lmax = -CUDART_INF_F;
    const size_t obase = (size_t)img * (N_OUT * N_OUT) + 8 * q;

    issue_tile(s[0], src, (tile0 & 31) * TILE_J, t);
    asm volatile("cp.async.commit_group;" ::: "memory");

#pragma unroll
    for (int tt = 0; tt < NT; tt++) {
        if (tt + 1 < NT) {
            issue_tile(s[(tt + 1) & 1], src, ((tile0 + tt + 1) & 31) * TILE_J, t);
            asm volatile("cp.async.commit_group;" ::: "memory");
            asm volatile("cp.async.wait_group 1;" ::: "memory");
        } else {
            asm volatile("cp.async.wait_group 0;" ::: "memory");
        }
        __syncthreads();

        const float (*sb)[SMEM_W] = s[tt & 1];

        // Vertical pass: v[a][c] = vertically filtered value for block-local
        // out row 4g+a at input col 4q-2+c  (c=0..7).
        float v[4][8];
#pragma unroll
        for (int a = 0; a < 4; a++)
#pragma unroll
            for (int c = 0; c < 8; c++) v[a][c] = 0.0f;

        const float WEv[4] = {WE0, WE1, WE2, WE3};
        const float WOv[4] = {WO0, WO1, WO2, WO3};

#pragma unroll
        for (int r = 0; r < 6; r++) {
            const float* row = &sb[2 * g + r][4 * q];   // 16B aligned
            const float4 A = *reinterpret_cast<const float4*>(row);
            const float4 B = *reinterpret_cast<const float4*>(row + 4);
            const float4 C = *reinterpret_cast<const float4*>(row + 8);
            // f[c] = smem col 4q+2+c, c=0..7  (input cols 4q-2..4q+5)
            const float f[8] = {A.z, A.w, B.x, B.y, B.z, B.w, C.x, C.y};
            if (r <= 3) {
                const float w = WEv[r];
#pragma unroll
                for (int c = 0; c < 8; c++) v[0][c] += w * f[c];
            }
            if (r >= 1 && r <= 4) {
                const float wo = WOv[r - 1];
                const float we = WEv[r - 1];
#pragma unroll
                for (int c = 0; c < 8; c++) {
                    v[1][c] += wo * f[c];
                    v[2][c] += we * f[c];
                }
            }
            if (r >= 2) {
                const float w = WOv[r - 2];
#pragma unroll
                for (int c = 0; c < 8; c++) v[3][c] += w * f[c];
            }
        }
        __syncthreads();   // smem reads done; buffer may be refilled next iter

        // Horizontal pass + epilogue (registers only).
        const int rbase = ((tile0 + tt) & 31) * 16 + 4 * g;
#pragma unroll
        for (int a = 0; a < 4; a++) {
            float o[8];
#pragma unroll
            for (int p = 0; p < 4; p++) {
                o[2 * p]     = WE0 * v[a][p]     + WE1 * v[a][p + 1] + WE2 * v[a][p + 2] + WE3 * v[a][p + 3];
                o[2 * p + 1] = WO0 * v[a][p + 1] + WO1 * v[a][p + 2] + WO2 * v[a][p + 3] + WO3 * v[a][p + 4];
            }
            if (WRITE) {
                float4 v0, v1;
                v0.x = fmaf(o[0], scale, bias); v0.y = fmaf(o[1], scale, bias);
                v0.z = fmaf(o[2], scale, bias); v0.w = fmaf(o[3], scale, bias);
                v1.x = fmaf(o[4], scale, bias); v1.y = fmaf(o[5], scale, bias);
                v1.z = fmaf(o[6], scale, bias); v1.w = fmaf(o[7], scale, bias);
                float* rp = out + obase + (size_t)(rbase + a) * N_OUT;
                *reinterpret_cast<float4*>(rp)     = v0;
                *reinterpret_cast<float4*>(rp + 4) = v1;
            } else {
#pragma unroll
                for (int c = 0; c < 8; c++) {
                    lmin = fminf(lmin, o[c]);
                    lmax = fmaxf(lmax, o[c]);
                }
            }
        }
    }

    if (!WRITE) {
#pragma unroll
        for (int off = 16; off > 0; off >>= 1) {
            lmin = fminf(lmin, __shfl_xor_sync(0xFFFFFFFFu, lmin, off));
            lmax = fmaxf(lmax, __shfl_xor_sync(0xFFFFFFFFu, lmax, off));
        }
        __shared__ float wmin[THREADS / 32], wmax[THREADS / 32];
        const int w = t >> 5, l = t & 31;
        if (l == 0) { wmin[w] = lmin; wmax[w] = lmax; }
        __syncthreads();
        if (t == 0) {
            float m = wmin[0], M = wmax[0];
#pragma unroll
            for (int i = 1; i < THREADS / 32; i++) {
                m = fminf(m, wmin[i]);
                M = fmaxf(M, wmax[i]);
            }
            atomicMin(&g_red[0], encf(m));
            atomicMin(&g_red[1], encf(-M));
        }
    }
}

extern "C" void kernel_launch(void* const* d_in, const int* in_sizes, int n_in,
                              void* d_out, int out_size) {
    const float* LL = (const float*)d_in[0];
    float* out = (float*)d_out;
    (void)in_sizes; (void)n_in; (void)out_size;

    static unsigned int* red_ptr = nullptr;
    if (!red_ptr) cudaGetSymbolAddress((void**)&red_ptr, g_red);

    cudaMemsetAsync(red_ptr, 0xFF, 2 * sizeof(unsigned int));
    qwt_up_kernel<false><<<GRID, THREADS>>>(LL, out);  // min/max pass
    qwt_up_kernel<true ><<<GRID, THREADS>>>(LL, out);  // normalize + write pass
}

// round 7
// speedup vs baseline: 1.5214x; 1.5214x over previous
#include <cuda_runtime.h>
#include <math_constants.h>

// out = minmax_normalize( bicubic_up2x( LL[:, 0:8] ) )
// All other iqwt terms carry sum(gh)=sum(fl)=sum(fh)=0 (f32 residue < 3e-7);
// the surviving sg^2 scalar cancels in the min-max normalization.
//
// memset node: g_red sentinels (both 0xFFFFFFFF).
// Pass 1: upsample (discard), min/max -> 2 atomics per block.
// Pass 2: recompute (input L2-resident), fused normalize.
// Thread owns 4 contiguous out cols x 8 out rows -> STG.128 fully coalesced.

#define THREADS 256
#define TILE_J  8             // input rows per block -> 16 output rows
#define IN_ROWS 12            // 8 + 4 halo
#define SMEM_W  264           // 4 pad | 256 | 4 pad  (aligned fill + windows)
#define N_IN    256
#define N_OUT   512
#define N_IMG   64
#define TILES_PER_IMG 32
#define GRID (N_IMG * TILES_PER_IMG)   // 2048

// bicubic a=-0.75, src = 0.5*i - 0.25
#define WE0 (-0.03515625f)
#define WE1 ( 0.26171875f)
#define WE2 ( 0.87890625f)
#define WE3 (-0.10546875f)
#define WO0 (-0.10546875f)
#define WO1 ( 0.87890625f)
#define WO2 ( 0.26171875f)
#define WO3 (-0.03515625f)

__device__ unsigned int g_red[2];   // [0]=min(enc(v)), [1]=min(enc(-v))

__device__ __forceinline__ unsigned int encf(float f) {
    unsigned int u = __float_as_uint(f);
    return (u & 0x80000000u) ? ~u : (u | 0x80000000u);
}
__device__ __forceinline__ float decf(unsigned int e) {
    unsigned int u = (e & 0x80000000u) ? (e ^ 0x80000000u) : ~e;
    return __uint_as_float(u);
}

template <bool WRITE>
__global__ __launch_bounds__(THREADS)
void qwt_up_kernel(const float* __restrict__ LL, float* __restrict__ out) {
    __shared__ __align__(16) float s[IN_ROWS][SMEM_W];

    const int t    = threadIdx.x;
    const int img  = blockIdx.x >> 5;        // 0..63
    const int tile = blockIdx.x & 31;        // 0..31
    const int b    = img >> 3;
    const int ch   = img & 7;                // lglg = LL channels 0..7
    const float* __restrict__ src = LL + (size_t)(b * 32 + ch) * (N_IN * N_IN);
    const int jbase = tile * TILE_J;

    float scale = 1.0f, bias = 0.0f;
    if (WRITE) {
        const float mn =  decf(g_red[0]);
        const float mx = -decf(g_red[1]);
        scale = 1.0f / (mx - mn);
        bias  = -mn * scale;
    }

    // ---- Fill: input col c -> smem col c+4. 768 float4 chunks, 3/thread,
    // coalesced LDG.128 + aligned STS.128.
#pragma unroll
    for (int i = 0; i < 3; i++) {
        const int f  = t + i * THREADS;      // 0..767
        const int rr = f >> 6;               // 0..11
        const int qc = f & 63;
        const int gr = min(max(jbase - 2 + rr, 0), N_IN - 1);
        *reinterpret_cast<float4*>(&s[rr][4 * qc + 4]) =
            *reinterpret_cast<const float4*>(src + gr * N_IN + 4 * qc);
    }
    // Replicate halo (input cols -2,-1 and 256,257).
    if (t < IN_ROWS) {
        const int gr = min(max(jbase - 2 + t, 0), N_IN - 1);
        const float v = src[gr * N_IN];
        s[t][2] = v; s[t][3] = v;
    } else if (t >= 128 && t < 128 + IN_ROWS) {
        const int rr = t - 128;
        const int gr = min(max(jbase - 2 + rr, 0), N_IN - 1);
        const float v = src[gr * N_IN + (N_IN - 1)];
        s[rr][260] = v; s[rr][261] = v;
    }
    __syncthreads();

    // ---- Thread (k, g): out cols 4k..4k+3, block-local out rows 8g..8g+7.
    const int k = t & 127;
    const int g = t >> 7;

    // Horizontal pass: input rows (block-local j) 4g-2 .. 4g+5 = smem rows
    // 4g .. 4g+7. hb[r] = h values at out cols 4k..4k+3 for that input row.
    float hb[8][4];
#pragma unroll
    for (int r = 0; r < 8; r++) {
        const float* rp = &s[4 * g + r][2 * k + 2];   // input cols 2k-2..
        const float2 z01 = *reinterpret_cast<const float2*>(rp);
        const float2 z23 = *reinterpret_cast<const float2*>(rp + 2);
        const float2 z45 = *reinterpret_cast<const float2*>(rp + 4);
        const float z0 = z01.x, z1 = z01.y, z2 = z23.x;
        const float z3 = z23.y, z4 = z45.x, z5 = z45.y;
        hb[r][0] = WE0 * z0 + WE1 * z1 + WE2 * z2 + WE3 * z3;   // out col 4k
        hb[r][1] = WO0 * z1 + WO1 * z2 + WO2 * z3 + WO3 * z4;   // 4k+1
        hb[r][2] = WE0 * z1 + WE1 * z2 + WE2 * z3 + WE3 * z4;   // 4k+2
        hb[r][3] = WO0 * z2 + WO1 * z3 + WO2 * z4 + WO3 * z5;   // 4k+3
    }

    // Vertical pass + epilogue, all in registers.
    float lmin =  CUDART_INF_F;
    float lmax = -CUDART_INF_F;
    const size_t obase = (size_t)img * (N_OUT * N_OUT) + 4 * k;
    const int rbase = tile * 16 + 8 * g;

#pragma unroll
    for (int a = 0; a < 8; a++) {
        const int ra = a >> 1;
        float o[4];
        if ((a & 1) == 0) {
#pragma unroll
            for (int c = 0; c < 4; c++)
                o[c] = WE0 * hb[ra][c] + WE1 * hb[ra + 1][c]
                     + WE2 * hb[ra + 2][c] + WE3 * hb[ra + 3][c];
        } else {
#pragma unroll
            for (int c = 0; c < 4; c++)
                o[c] = WO0 * hb[ra + 1][c] + WO1 * hb[ra + 2][c]
                     + WO2 * hb[ra + 3][c] + WO3 * hb[ra + 4][c];
        }
        if (WRITE) {
            float4 v;
            v.x = fmaf(o[0], scale, bias); v.y = fmaf(o[1], scale, bias);
            v.z = fmaf(o[2], scale, bias); v.w = fmaf(o[3], scale, bias);
            *reinterpret_cast<float4*>(out + obase + (size_t)(rbase + a) * N_OUT) = v;
        } else {
            lmin = fminf(lmin, fminf(fminf(o[0], o[1]), fminf(o[2], o[3])));
            lmax = fmaxf(lmax, fmaxf(fmaxf(o[0], o[1]), fmaxf(o[2], o[3])));
        }
    }

    if (!WRITE) {
#pragma unroll
        for (int off = 16; off > 0; off >>= 1) {
            lmin = fminf(lmin, __shfl_xor_sync(0xFFFFFFFFu, lmin, off));
            lmax = fmaxf(lmax, __shfl_xor_sync(0xFFFFFFFFu, lmax, off));
        }
        __shared__ float wmin[THREADS / 32], wmax[THREADS / 32];
        const int w = t >> 5, l = t & 31;
        if (l == 0) { wmin[w] = lmin; wmax[w] = lmax; }
        __syncthreads();
        if (t == 0) {
            float m = wmin[0], M = wmax[0];
#pragma unroll
            for (int i = 1; i < THREADS / 32; i++) {
                m = fminf(m, wmin[i]);
                M = fmaxf(M, wmax[i]);
            }
            atomicMin(&g_red[0], encf(m));
            atomicMin(&g_red[1], encf(-M));
        }
    }
}

extern "C" void kernel_launch(void* const* d_in, const int* in_sizes, int n_in,
                              void* d_out, int out_size) {
    const float* LL = (const float*)d_in[0];
    float* out = (float*)d_out;
    (void)in_sizes; (void)n_in; (void)out_size;

    static unsigned int* red_ptr = nullptr;
    if (!red_ptr) cudaGetSymbolAddress((void**)&red_ptr, g_red);

    cudaMemsetAsync(red_ptr, 0xFF, 2 * sizeof(unsigned int));
    qwt_up_kernel<false><<<GRID, THREADS>>>(LL, out);  // min/max pass
    qwt_up_kernel<true ><<<GRID, THREADS>>>(LL, out);  // normalize + write pass
}